// round 7
// baseline (speedup 1.0000x reference)
#include <cuda_runtime.h>
#include <cstdint>

// Problem constants
#define BB   64
#define TT   2048
#define II   200
#define HH   100
#define G4   400   // 4*H
#define HP   104   // padded h length (pad = 0)

// Scratch: xg[t][b][j] (t-major so scan CTA b streams coalesced rows), ~210MB.
__device__ float g_xg[(size_t)TT * BB * G4];

// ---- packed fp32x2 helpers ---------------------------------------------
union f2u { float2 f; unsigned long long u; };
union f4u { float4 f; ulonglong2 u; };

__device__ __forceinline__ unsigned long long ffma2(unsigned long long a,
                                                    unsigned long long b,
                                                    unsigned long long c) {
    unsigned long long d;
    asm("fma.rn.f32x2 %0, %1, %2, %3;" : "=l"(d) : "l"(a), "l"(b), "l"(c));
    return d;
}
__device__ __forceinline__ unsigned long long fadd2(unsigned long long a,
                                                    unsigned long long b) {
    unsigned long long d;
    asm("add.rn.f32x2 %0, %1, %2;" : "=l"(d) : "l"(a), "l"(b));
    return d;
}

__device__ __forceinline__ float tanh_(float x) {
    return __fdividef(2.0f, 1.0f + __expf(-2.0f * x)) - 1.0f;
}

// ---- kernel 1: input projection (register-blocked SIMT GEMM) -----------
// C[131072, 400] = x[131072, 200] @ W_ih^T  (+bias) -> g_xg[t][b][col]
// CTA tile: 64 rows x 100 cols (grid 2048 x 4). 200 threads, thread tile 8x4.
#define KC 20
#define AS_STRIDE 68   // 68*4=272B, 16B aligned

__global__ __launch_bounds__(200, 4)
void proj_kernel(const float* __restrict__ x,
                 const float* __restrict__ Wih,
                 const float* __restrict__ bih,
                 const float* __restrict__ bhh) {
    __shared__ float As[KC * AS_STRIDE];   // As[k][r], 5.44 KB
    __shared__ float Bs[KC * HH];          // Bs[k][jc], 8 KB

    const int tid  = threadIdx.x;
    const int tx   = tid % 25;             // col group: cols tx*4 .. tx*4+3
    const int ty   = tid / 25;             // row group: rows ty*8 .. ty*8+7
    const int row0 = blockIdx.x * 64;
    const int c0   = blockIdx.y * HH;      // global column base (0/100/200/300)

    unsigned long long acc[8][2];
    #pragma unroll
    for (int r = 0; r < 8; ++r) { acc[r][0] = 0ULL; acc[r][1] = 0ULL; }

    for (int cch = 0; cch < II / KC; ++cch) {
        const int k0 = cch * KC;
        __syncthreads();   // previous chunk fully consumed

        // Stage A: 64 rows x 20 k, transposed to As[k][r]. 320 float4 loads.
        for (int idx = tid; idx < 64 * (KC / 4); idx += 200) {
            int r = idx / (KC / 4);
            int q = idx - r * (KC / 4);
            float4 v = *(const float4*)&x[(size_t)(row0 + r) * II + k0 + 4 * q];
            As[(4 * q + 0) * AS_STRIDE + r] = v.x;
            As[(4 * q + 1) * AS_STRIDE + r] = v.y;
            As[(4 * q + 2) * AS_STRIDE + r] = v.z;
            As[(4 * q + 3) * AS_STRIDE + r] = v.w;
        }
        // Stage B (transposing): thread t<100 owns W_ih row j=c0+t (L2-resident)
        if (tid < HH) {
            const float* wrow = &Wih[(size_t)(c0 + tid) * II + k0];
            #pragma unroll
            for (int q = 0; q < KC / 4; ++q) {
                float4 v = *(const float4*)&wrow[4 * q];
                Bs[(4 * q + 0) * HH + tid] = v.x;
                Bs[(4 * q + 1) * HH + tid] = v.y;
                Bs[(4 * q + 2) * HH + tid] = v.z;
                Bs[(4 * q + 3) * HH + tid] = v.w;
            }
        }
        __syncthreads();

        #pragma unroll 4
        for (int k = 0; k < KC; ++k) {
            f4u a0, a1, w0;
            a0.f = *(const float4*)&As[k * AS_STRIDE + ty * 8];
            a1.f = *(const float4*)&As[k * AS_STRIDE + ty * 8 + 4];
            w0.f = *(const float4*)&Bs[k * HH + tx * 4];
            float ar[8] = {a0.f.x, a0.f.y, a0.f.z, a0.f.w,
                           a1.f.x, a1.f.y, a1.f.z, a1.f.w};
            #pragma unroll
            for (int r = 0; r < 8; ++r) {
                f2u av; av.f.x = ar[r]; av.f.y = ar[r];
                acc[r][0] = ffma2(av.u, w0.u.x, acc[r][0]);
                acc[r][1] = ffma2(av.u, w0.u.y, acc[r][1]);
            }
        }
    }

    // Epilogue: add bias, scatter rows to g_xg[t][b][col]
    const int col = c0 + tx * 4;
    f4u bi, bh;
    bi.f = *(const float4*)&bih[col];
    bh.f = *(const float4*)&bhh[col];
    float4 bias = make_float4(bi.f.x + bh.f.x, bi.f.y + bh.f.y,
                              bi.f.z + bh.f.z, bi.f.w + bh.f.w);

    #pragma unroll
    for (int r = 0; r < 8; ++r) {
        int m = row0 + ty * 8 + r;
        int b = m >> 11;           // m / 2048
        int t = m & 2047;
        f2u p0, p1;
        p0.u = acc[r][0]; p1.u = acc[r][1];
        float4 o = make_float4(p0.f.x + bias.x, p0.f.y + bias.y,
                               p1.f.x + bias.z, p1.f.y + bias.w);
        *(float4*)&g_xg[((size_t)t * BB + b) * G4 + col] = o;
    }
}

// ---- kernel 2: sequential LSTM scan (octet decomposition) ---------------
// One CTA per batch row, 800 threads (25 warps). Threads 8j..8j+7 own unit
// j: sub&3 = gate (i,f,g,o), sub>>2 = half. Each thread does a 52-float
// half-dot (13 LDS.128 + 26 FFMA2) -> halves combined via shfl_xor(4,w=8),
// gates via quad shfl. h double-buffered, padded to 104 (pad==0), ONE
// barrier per step. xg prefetched 2 steps ahead (ring).
__global__ __launch_bounds__(800, 1)
void scan_kernel(const float* __restrict__ Whh, float* __restrict__ out) {
    const int b    = blockIdx.x;
    const int tid  = threadIdx.x;
    const int j    = tid >> 3;     // hidden unit 0..99
    const int sub  = tid & 7;      // octet lane
    const int g    = sub & 3;      // gate: 0=i 1=f 2=g 3=o
    const int hsel = sub >> 2;     // half: 0 -> h[0:52), 1 -> h[52:104)

    __shared__ __align__(16) float h_sh[2][HP];

    // W_hh half-row in registers: 13 float4 covering cols hsel*52..+51,
    // zero-padded past col 99.
    f4u wreg[13];
    {
        const float* wrow = Whh + (size_t)(g * HH + j) * HH;
        #pragma unroll
        for (int i = 0; i < 13; ++i) {
            float tmp[4];
            #pragma unroll
            for (int k = 0; k < 4; ++k) {
                int idx = hsel * 52 + 4 * i + k;
                tmp[k] = (idx < HH) ? wrow[idx] : 0.0f;
            }
            wreg[i].f = make_float4(tmp[0], tmp[1], tmp[2], tmp[3]);
        }
    }

    float c = 0.0f, hval = 0.0f;
    if (tid < HP) { h_sh[0][tid] = 0.0f; h_sh[1][tid] = 0.0f; }
    __syncthreads();

    const float* xg = g_xg + (size_t)b * G4 + (g * HH + j);
    const size_t tstride = (size_t)BB * G4;

    float cur0 = 0.f, cur1 = 0.f, nxt0 = 0.f, nxt1 = 0.f;
    if (hsel == 0) {
        cur0 = __ldcs(&xg[0]);
        cur1 = __ldcs(&xg[tstride]);
    }

    int p = 0;
    for (int tg = 0; tg < TT; tg += 2) {
        if (hsel == 0) {   // prefetch 2 steps ahead
            int t2 = tg + 2; t2 = (t2 < TT) ? t2 : (TT - 1);
            int t3 = tg + 3; t3 = (t3 < TT) ? t3 : (TT - 1);
            nxt0 = __ldcs(&xg[(size_t)t2 * tstride]);
            nxt1 = __ldcs(&xg[(size_t)t3 * tstride]);
        }

        #pragma unroll
        for (int i2 = 0; i2 < 2; ++i2) {
            float xv = i2 ? cur1 : cur0;

            unsigned long long A0 = 0ULL, A1 = 0ULL;
            const float4* hb = (const float4*)(h_sh[p] + hsel * 52);
            #pragma unroll
            for (int i = 0; i < 13; ++i) {
                f4u h4; h4.f = hb[i];             // broadcast LDS.128
                A0 = ffma2(wreg[i].u.x, h4.u.x, A0);
                A1 = ffma2(wreg[i].u.y, h4.u.y, A1);
            }
            f2u s; s.u = fadd2(A0, A1);
            float partial = s.f.x + s.f.y;
            if (hsel == 0) partial += xv;

            // combine halves within octet (lanes differing in bit 2)
            float total = partial + __shfl_xor_sync(0xffffffffu, partial, 4, 8);

            // branch-free activation: g==2 -> tanh = 2*sig(2x)-1, else sigmoid
            bool is_t = (g == 2);
            float xx = is_t ? 2.0f * total : total;
            float sg = __fdividef(1.0f, 1.0f + __expf(-xx));
            float a  = is_t ? fmaf(2.0f, sg, -1.0f) : sg;

            // quad combine (gates of this unit live in lanes sub 0..3)
            float fg = __shfl_down_sync(0xffffffffu, a, 1, 4);
            float gg = __shfl_down_sync(0xffffffffu, a, 2, 4);
            float og = __shfl_down_sync(0xffffffffu, a, 3, 4);
            if (sub == 0) {
                c    = fg * c + a * gg;
                hval = og * tanh_(c);
                h_sh[p ^ 1][j] = hval;            // write OTHER buffer
            }
            __syncthreads();
            p ^= 1;
        }

        cur0 = nxt0;
        cur1 = nxt1;
    }

    if (sub == 0) out[b * HH + j] = hval;
}

// ---- launch ------------------------------------------------------------
extern "C" void kernel_launch(void* const* d_in, const int* in_sizes, int n_in,
                              void* d_out, int out_size) {
    const float* x   = (const float*)d_in[0];   // [64,2048,200]
    const float* Wih = (const float*)d_in[1];   // [400,200]
    const float* Whh = (const float*)d_in[2];   // [400,100]
    const float* bih = (const float*)d_in[3];   // [400]
    const float* bhh = (const float*)d_in[4];   // [400]
    float* out = (float*)d_out;                 // [64,100]

    proj_kernel<<<dim3(TT * BB / 64, 4), 200>>>(x, Wih, bih, bhh);
    scan_kernel<<<BB, 800>>>(Whh, out);
}

// round 8
// speedup vs baseline: 1.0562x; 1.0562x over previous
#include <cuda_runtime.h>
#include <cstdint>

// Problem constants
#define BB   64
#define TT   2048
#define II   200
#define HH   100
#define G4   400   // 4*H
#define NPROJ 84   // producer CTAs (blockIdx 0..83)
#define NSCAN 64   // consumer CTAs (blockIdx 84..147)
#define NCTA  (NPROJ + NSCAN)

// Scratch: xg[t][b][j] (t-major), ~210MB. Produced by proj role, consumed by scan.
__device__ float g_xg[(size_t)TT * BB * G4];
// Per-timestep ready counters (4 column-tiles each). Reset every launch.
__device__ int g_ready[TT];

// ---- packed fp32x2 helpers ---------------------------------------------
union f2u { float2 f; unsigned long long u; };
union f4u { float4 f; ulonglong2 u; };

__device__ __forceinline__ unsigned long long ffma2(unsigned long long a,
                                                    unsigned long long b,
                                                    unsigned long long c) {
    unsigned long long d;
    asm("fma.rn.f32x2 %0, %1, %2, %3;" : "=l"(d) : "l"(a), "l"(b), "l"(c));
    return d;
}
__device__ __forceinline__ unsigned long long fadd2(unsigned long long a,
                                                    unsigned long long b) {
    unsigned long long d;
    asm("add.rn.f32x2 %0, %1, %2;" : "=l"(d) : "l"(a), "l"(b));
    return d;
}
__device__ __forceinline__ float tanh_(float x) {
    return __fdividef(2.0f, 1.0f + __expf(-2.0f * x)) - 1.0f;
}
__device__ __forceinline__ int ld_acq(const int* p) {
    int v;
    asm volatile("ld.acquire.gpu.global.b32 %0, [%1];" : "=r"(v) : "l"(p));
    return v;
}

// ---- shared memory union ------------------------------------------------
#define KC 40
#define ASTR 68          // padded A stride (floats), 272B (16B aligned)
struct SmemProj { float As[KC * ASTR]; float Bs[KC * HH]; };   // 10.9 + 16 KB
struct SmemScan { float h[2][HH]; };
union SmemU { SmemProj p; SmemScan s; };

// ---- flag reset (runs before fused kernel each launch) ------------------
__global__ void reset_kernel() {
    int i = blockIdx.x * 256 + threadIdx.x;
    if (i < TT) g_ready[i] = 0;
}

// ---- producer role: input projection ------------------------------------
// One tile = one timestep t x 100 cols x all 64 batches. 8192 tiles over 84
// CTAs, swept in ascending-t order. After a tile: fence + atomicAdd(ready[t]).
__device__ __forceinline__ void proj_role(SmemProj& sm,
                                          const float* __restrict__ x,
                                          const float* __restrict__ Wih,
                                          const float* __restrict__ bih,
                                          const float* __restrict__ bhh) {
    const int tid = threadIdx.x;
    const int tx  = tid % 25;        // cols tx*4 .. tx*4+3 (within 100)
    const int ty  = tid / 25;        // batches ty*4 .. ty*4+3
    const int cta = blockIdx.x;

    for (int tile = cta; tile < TT * 4; tile += NPROJ) {
        const int t  = tile >> 2;
        const int c0 = (tile & 3) * HH;

        unsigned long long acc[4][2];
        #pragma unroll
        for (int r = 0; r < 4; ++r) { acc[r][0] = 0ULL; acc[r][1] = 0ULL; }

        for (int ch = 0; ch < II / KC; ++ch) {
            const int k0 = ch * KC;
            __syncthreads();   // previous chunk / previous tile consumed

            // Stage A: x[b][t][k0..k0+39] for b=0..63, transposed to As[k][b]
            for (int idx = tid; idx < 64 * (KC / 4); idx += 400) {
                int r = idx / (KC / 4);
                int q = idx - r * (KC / 4);
                float4 v = *(const float4*)&x[((size_t)r * TT + t) * II + k0 + 4 * q];
                sm.As[(4 * q + 0) * ASTR + r] = v.x;
                sm.As[(4 * q + 1) * ASTR + r] = v.y;
                sm.As[(4 * q + 2) * ASTR + r] = v.z;
                sm.As[(4 * q + 3) * ASTR + r] = v.w;
            }
            // Stage B (transposing): thread t<100 owns W_ih row c0+t (L2-res.)
            if (tid < HH) {
                const float* wrow = &Wih[(size_t)(c0 + tid) * II + k0];
                #pragma unroll
                for (int q = 0; q < KC / 4; ++q) {
                    float4 v = *(const float4*)&wrow[4 * q];
                    sm.Bs[(4 * q + 0) * HH + tid] = v.x;
                    sm.Bs[(4 * q + 1) * HH + tid] = v.y;
                    sm.Bs[(4 * q + 2) * HH + tid] = v.z;
                    sm.Bs[(4 * q + 3) * HH + tid] = v.w;
                }
            }
            __syncthreads();

            #pragma unroll 4
            for (int k = 0; k < KC; ++k) {
                f4u a4, w4;
                a4.f = *(const float4*)&sm.As[k * ASTR + ty * 4];
                w4.f = *(const float4*)&sm.Bs[k * HH + tx * 4];
                float ar[4] = {a4.f.x, a4.f.y, a4.f.z, a4.f.w};
                #pragma unroll
                for (int r = 0; r < 4; ++r) {
                    f2u av; av.f.x = ar[r]; av.f.y = ar[r];
                    acc[r][0] = ffma2(av.u, w4.u.x, acc[r][0]);
                    acc[r][1] = ffma2(av.u, w4.u.y, acc[r][1]);
                }
            }
        }

        // Epilogue: bias + store to g_xg[t][b][col]
        const int col = c0 + tx * 4;
        float4 bi = *(const float4*)&bih[col];
        float4 bh = *(const float4*)&bhh[col];
        float4 bias = make_float4(bi.x + bh.x, bi.y + bh.y, bi.z + bh.z, bi.w + bh.w);
        #pragma unroll
        for (int r = 0; r < 4; ++r) {
            int b = ty * 4 + r;
            f2u p0, p1; p0.u = acc[r][0]; p1.u = acc[r][1];
            float4 o = make_float4(p0.f.x + bias.x, p0.f.y + bias.y,
                                   p1.f.x + bias.z, p1.f.y + bias.w);
            *(float4*)&g_xg[((size_t)t * BB + b) * G4 + col] = o;
        }

        __threadfence();     // each thread's stores visible at gpu scope
        __syncthreads();     // ... before tid0 publishes
        if (tid == 0) atomicAdd(&g_ready[t], 1);
    }
}

// ---- consumer role: sequential LSTM scan --------------------------------
// One CTA per batch, 400 threads, quad layout (threads 4j..4j+3 = gates
// i,f,g,o of unit j). h double-buffered, ONE barrier/step. Branch-free
// tail: xor-shfl exchanges all 4 gate values; every quad lane redundantly
// tracks c and h. xg prefetched 4 steps ahead; ready-flags verified one
// group EARLY so the check latency is off the critical path.
__device__ __forceinline__ void wait4(int t0, int sel, unsigned wmask) {
    int idx = t0 + sel;
    idx = (idx < TT) ? idx : (TT - 1);
    const int* fp = &g_ready[idx];
    while (!__all_sync(wmask, ld_acq(fp) == 4)) { }
}

__device__ __forceinline__ void scan_role(SmemScan& sm,
                                          const float* __restrict__ Whh,
                                          float* __restrict__ out) {
    const int b    = blockIdx.x - NPROJ;
    const int tid  = threadIdx.x;
    const int j    = tid >> 2;
    const int g    = tid & 3;
    const int lane = tid & 31;
    const unsigned qmask = 0xFu << (lane & ~3);
    const int warpbase = tid & ~31;
    const int nl = (400 - warpbase >= 32) ? 32 : (400 - warpbase);
    const unsigned wmask = (nl == 32) ? 0xffffffffu : ((1u << nl) - 1u);

    // W_hh row (g*100 + j) in registers: 25 float4
    f4u wreg[HH / 4];
    const float4* wr = (const float4*)(Whh + (size_t)(g * HH + j) * HH);
    #pragma unroll
    for (int q = 0; q < HH / 4; ++q) wreg[q].f = wr[q];

    float c = 0.0f, hval = 0.0f;
    if (tid < HH) sm.h[0][tid] = 0.0f;
    __syncthreads();

    const float* xg = g_xg + (size_t)b * G4 + (g * HH + j);
    const size_t ts = (size_t)BB * G4;

    float cur[4], nxt[4];
    wait4(0, g, wmask);                        // flags 0..3
    #pragma unroll
    for (int i = 0; i < 4; ++i) cur[i] = __ldcg(&xg[(size_t)i * ts]);
    wait4(4, g, wmask);                        // flags 4..7 (for first nxt)

    int p = 0;
    for (int tg = 0; tg < TT; tg += 4) {
        // issue next group's loads (flags already verified last iteration)
        #pragma unroll
        for (int i = 0; i < 4; ++i) {
            int t = tg + 4 + i; t = (t < TT) ? t : (TT - 1);
            nxt[i] = __ldcg(&xg[(size_t)t * ts]);
        }
        // verify flags for the group after that (overlaps with compute)
        wait4(tg + 8, g, wmask);

        #pragma unroll
        for (int i = 0; i < 4; ++i) {
            unsigned long long a0 = 0ULL, a1 = 0ULL, a2 = 0ULL, a3 = 0ULL;
            const float4* hb = (const float4*)sm.h[p];
            #pragma unroll
            for (int q = 0; q < HH / 4; ++q) {
                f4u h4; h4.f = hb[q];          // broadcast LDS.128
                if (q & 1) {
                    a2 = ffma2(wreg[q].u.x, h4.u.x, a2);
                    a3 = ffma2(wreg[q].u.y, h4.u.y, a3);
                } else {
                    a0 = ffma2(wreg[q].u.x, h4.u.x, a0);
                    a1 = ffma2(wreg[q].u.y, h4.u.y, a1);
                }
            }
            f2u s0, s1;
            s0.u = fadd2(a0, a2);
            s1.u = fadd2(a1, a3);
            float gate = (s0.f.x + s0.f.y) + (s1.f.x + s1.f.y) + cur[i];

            // branch-free activation: g==2 -> tanh, else sigmoid
            bool is_t = (g == 2);
            float xx = is_t ? 2.0f * gate : gate;
            float sg = __fdividef(1.0f, 1.0f + __expf(-xx));
            float a  = is_t ? fmaf(2.0f, sg, -1.0f) : sg;

            // exchange all 4 gate values within the quad (no divergence)
            float x1 = __shfl_xor_sync(qmask, a, 1, 4);
            float x2 = __shfl_xor_sync(qmask, a, 2, 4);
            float x3 = __shfl_xor_sync(qmask, a, 3, 4);
            float ig = (g == 0) ? a : (g == 1) ? x1 : (g == 2) ? x2 : x3;
            float fg = (g == 1) ? a : (g == 0) ? x1 : (g == 3) ? x2 : x3;
            float gg = (g == 2) ? a : (g == 3) ? x1 : (g == 0) ? x2 : x3;
            float og = (g == 3) ? a : (g == 2) ? x1 : (g == 1) ? x2 : x3;

            // every quad lane redundantly tracks c and h (identical values)
            c    = fg * c + ig * gg;
            hval = og * tanh_(c);
            sm.h[p ^ 1][j] = hval;             // 4 lanes, same addr, same value
            __syncthreads();
            p ^= 1;
        }

        #pragma unroll
        for (int i = 0; i < 4; ++i) cur[i] = nxt[i];
    }

    if (g == 0) out[b * HH + j] = hval;
}

// ---- fused persistent kernel --------------------------------------------
__global__ __launch_bounds__(400, 1)
void fused_kernel(const float* __restrict__ x,
                  const float* __restrict__ Wih,
                  const float* __restrict__ Whh,
                  const float* __restrict__ bih,
                  const float* __restrict__ bhh,
                  float* __restrict__ out) {
    __shared__ SmemU sm;
    if (blockIdx.x < NPROJ) {
        proj_role(sm.p, x, Wih, bih, bhh);
    } else {
        scan_role(sm.s, Whh, out);
    }
}

// ---- launch ------------------------------------------------------------
extern "C" void kernel_launch(void* const* d_in, const int* in_sizes, int n_in,
                              void* d_out, int out_size) {
    const float* x   = (const float*)d_in[0];   // [64,2048,200]
    const float* Wih = (const float*)d_in[1];   // [400,200]
    const float* Whh = (const float*)d_in[2];   // [400,100]
    const float* bih = (const float*)d_in[3];   // [400]
    const float* bhh = (const float*)d_in[4];   // [400]
    float* out = (float*)d_out;                 // [64,100]

    reset_kernel<<<(TT + 255) / 256, 256>>>();
    fused_kernel<<<NCTA, 400>>>(x, Wih, Whh, bih, bhh, out);
}